// round 6
// baseline (speedup 1.0000x reference)
#include <cuda_runtime.h>
#include <cuda_bf16.h>

// HungarianMatcher cost tensor C[16,900,800], nc=256.
// R5: 512 threads, TILE_R=16 (one softmax row per warp), NT_PER=2 targets per
// thread with full xyxy hoisted into registers (9 regs/target). Targets
// __launch_bounds__(512,2) -> <=64 regs -> 32 warps/SM (occ ~50%) to push
// warp-issue past R4's 72%. Lane waste in main loop drops 12% -> 4%.

constexpr int NC      = 256;
constexpr int TILE_R  = 16;    // query rows per block (one per warp)
constexpr int THREADS = 512;
constexpr int NT_PER  = 2;     // targets per thread (800 = 400 threads * 2)

constexpr float EPS = 1e-7f;

__global__ __launch_bounds__(THREADS, 2)
void matcher_cost_kernel(const float* __restrict__ logits,   // [N, NC]
                         const float* __restrict__ pboxes,   // [N, 4]
                         const int*   __restrict__ labels,   // [nt]
                         const float* __restrict__ tboxes,   // [nt, 4]
                         float*       __restrict__ out,      // [N, nt]
                         int n_rows, int nt)
{
    __shared__ float  s_prob[TILE_R][NC];   // 16KB softmax probs
    __shared__ float4 s_pred[TILE_R][3];    // {cx,cy,w,h},{x0,y0,x1,y1},{area}

    const int tid  = threadIdx.x;
    const int lane = tid & 31;
    const int warp = tid >> 5;
    const int n0   = blockIdx.x * TILE_R;

    // --- This thread's 2 targets -> registers (9 per target, fully derived) ---
    const int  mbase = tid * NT_PER;
    const bool act   = (mbase + NT_PER) <= nt;   // threads 0..399 for nt=800
    float tcx[NT_PER], tcy[NT_PER], tw[NT_PER], th[NT_PER];
    float tx0[NT_PER], ty0[NT_PER], tx1[NT_PER], ty1[NT_PER], ta[NT_PER];
    int   lob[NT_PER];                            // label byte offsets
    if (act) {
        const float4* tb4 = reinterpret_cast<const float4*>(tboxes);
        int2 lb = reinterpret_cast<const int2*>(labels)[tid];
        lob[0] = lb.x * 4; lob[1] = lb.y * 4;
        #pragma unroll
        for (int j = 0; j < NT_PER; j++) {
            float4 b = tb4[mbase + j];
            tcx[j] = b.x; tcy[j] = b.y; tw[j] = b.z; th[j] = b.w;
            float hw = 0.5f * b.z, hh = 0.5f * b.w;
            tx0[j] = b.x - hw; ty0[j] = b.y - hh;
            tx1[j] = b.x + hw; ty1[j] = b.y + hh;
            ta[j]  = b.z * b.w;
        }
    }

    // --- Softmax: warp w owns row n0+w (256 classes, 8/lane) ---
    const int n = n0 + warp;
    if (n < n_rows) {
        const float4* lr4 = reinterpret_cast<const float4*>(logits + (size_t)n * NC);
        float4 a = lr4[lane];
        float4 b = lr4[lane + 32];
        float mx = fmaxf(fmaxf(fmaxf(a.x, a.y), fmaxf(a.z, a.w)),
                         fmaxf(fmaxf(b.x, b.y), fmaxf(b.z, b.w)));
        #pragma unroll
        for (int o = 16; o > 0; o >>= 1)
            mx = fmaxf(mx, __shfl_xor_sync(0xffffffffu, mx, o));
        a.x = __expf(a.x - mx); a.y = __expf(a.y - mx);
        a.z = __expf(a.z - mx); a.w = __expf(a.w - mx);
        b.x = __expf(b.x - mx); b.y = __expf(b.y - mx);
        b.z = __expf(b.z - mx); b.w = __expf(b.w - mx);
        float sum = (a.x + a.y) + (a.z + a.w) + (b.x + b.y) + (b.z + b.w);
        #pragma unroll
        for (int o = 16; o > 0; o >>= 1)
            sum += __shfl_xor_sync(0xffffffffu, sum, o);
        float inv = __fdividef(1.0f, sum);
        a.x *= inv; a.y *= inv; a.z *= inv; a.w *= inv;
        b.x *= inv; b.y *= inv; b.z *= inv; b.w *= inv;
        float4* pr = reinterpret_cast<float4*>(s_prob[warp]);
        pr[lane]      = a;
        pr[lane + 32] = b;

        if (lane == 0) {
            float4 pb = reinterpret_cast<const float4*>(pboxes)[n];
            float hw = 0.5f * pb.z, hh = 0.5f * pb.w;
            s_pred[warp][0] = pb;
            s_pred[warp][1] = make_float4(pb.x - hw, pb.y - hh, pb.x + hw, pb.y + hh);
            s_pred[warp][2] = make_float4(pb.z * pb.w, 0.f, 0.f, 0.f);
        }
    }
    __syncthreads();

    const int rmax = min(TILE_R, n_rows - n0);

    if (act) {
        // --- Fast path: unrolled rows, 2 targets in registers ---
        float* orow = out + (size_t)n0 * nt + mbase;
        #pragma unroll
        for (int r = 0; r < TILE_R; r++) {
            if (r >= rmax) break;
            const float4 pc = s_pred[r][0];   // broadcast LDS.128
            const float4 px = s_pred[r][1];
            const float  pa = s_pred[r][2].x;
            const char* prb = reinterpret_cast<const char*>(s_prob[r]);

            float res[NT_PER];
            #pragma unroll
            for (int j = 0; j < NT_PER; j++) {
                float p = *reinterpret_cast<const float*>(prb + lob[j]);

                float l1 = fabsf(pc.x - tcx[j]) + fabsf(pc.y - tcy[j])
                         + fabsf(pc.z - tw[j])  + fabsf(pc.w - th[j]);

                float ix = fminf(px.z, tx1[j]) - fmaxf(px.x, tx0[j]);
                float iy = fminf(px.w, ty1[j]) - fmaxf(px.y, ty0[j]);
                float inter = fmaxf(ix, 0.f) * fmaxf(iy, 0.f);
                float uni   = pa + ta[j] - inter;

                // enclosing box via min/max sum identity: cx = (pw+tw) - ix
                float cxv = (pc.z + tw[j]) - ix;
                float cyv = (pc.w + th[j]) - iy;
                float ca  = cxv * cyv;

                // giou = inter/u - (ca-uni)/c == (inter*c + (uni-ca)*u)/(u*c)
                float u = uni + EPS;
                float c = ca + EPS;
                float num = fmaf(uni - ca, u, inter * c);
                float giou = __fdividef(num, u * c);

                res[j] = fmaf(-2.f, giou, fmaf(5.f, l1, -p));
            }
            *reinterpret_cast<float2*>(orow) = make_float2(res[0], res[1]);
            orow += nt;
        }
    } else if (mbase < nt) {
        // generic tail (nt odd; unused for nt=800)
        for (int j = 0; j < NT_PER && mbase + j < nt; j++) {
            int m = mbase + j;
            float4 b = reinterpret_cast<const float4*>(tboxes)[m];
            int lb = labels[m];
            float hw = 0.5f * b.z, hh = 0.5f * b.w;
            float bx0 = b.x - hw, by0 = b.y - hh, bx1 = b.x + hw, by1 = b.y + hh;
            float bar = b.z * b.w;
            for (int r = 0; r < rmax; r++) {
                float4 pc = s_pred[r][0];
                float4 px = s_pred[r][1];
                float  pa = s_pred[r][2].x;
                float p = s_prob[r][lb];
                float l1 = fabsf(pc.x - b.x) + fabsf(pc.y - b.y)
                         + fabsf(pc.z - b.z) + fabsf(pc.w - b.w);
                float ix = fminf(px.z, bx1) - fmaxf(px.x, bx0);
                float iy = fminf(px.w, by1) - fmaxf(px.y, by0);
                float inter = fmaxf(ix, 0.f) * fmaxf(iy, 0.f);
                float uni = pa + bar - inter;
                float iou = __fdividef(inter, uni + EPS);
                float cxv = fmaxf(px.z, bx1) - fminf(px.x, bx0);
                float cyv = fmaxf(px.w, by1) - fminf(px.y, by0);
                float ca = cxv * cyv;
                float giou = iou - __fdividef(ca - uni, ca + EPS);
                out[(size_t)(n0 + r) * nt + m] = 5.f * l1 - p - 2.f * giou;
            }
        }
    }
}

extern "C" void kernel_launch(void* const* d_in, const int* in_sizes, int n_in,
                              void* d_out, int out_size)
{
    const float* logits = (const float*)d_in[0];
    const float* pboxes = (const float*)d_in[1];
    const int*   labels = (const int*)  d_in[2];
    const float* tboxes = (const float*)d_in[3];
    float*       out    = (float*)d_out;

    const int n_rows = in_sizes[1] / 4;   // 14400
    const int nt     = in_sizes[2];       // 800

    const int blocks = (n_rows + TILE_R - 1) / TILE_R;
    matcher_cost_kernel<<<blocks, THREADS>>>(logits, pboxes, labels, tboxes,
                                             out, n_rows, nt);
}